// round 10
// baseline (speedup 1.0000x reference)
#include <cuda_runtime.h>
#include <cstdint>

// Problem constants (fixed by the reference): N=262144 output rows, D=128 f32.
// M = 1048576 value rows, sorted_index is sorted -> segmented sum, no atomics.

#define ROWS_PER_BLOCK 16          // 16 warps/block, warp-per-row
#define THREADS (32 * ROWS_PER_BLOCK)

// Fused kernel: block computes its own segment boundaries (17 parallel binary
// searches into shared memory), then each warp does a streaming segmented sum
// for one output row (D=128 floats = 32 float4 = one per lane).
__global__ void __launch_bounds__(THREADS)
fused_scatter_add_kernel(const int*    __restrict__ idx,      // [M] sorted int32
                         const float4* __restrict__ self_t,   // [N,32] float4
                         const float4* __restrict__ value,    // [M,32] float4
                         float4*       __restrict__ out,      // [N,32] float4
                         int M, int Nrows) {
    __shared__ int s_bounds[ROWS_PER_BLOCK + 1];

    const int r0 = blockIdx.x * ROWS_PER_BLOCK;
    const int t  = threadIdx.x;

    // Phase 1: 17 threads compute lower_bound(idx, r0 + t) in parallel.
    if (t <= ROWS_PER_BLOCK) {
        int n = r0 + t;
        if (n > Nrows) n = Nrows;     // clamp (also handles exact-tail block)
        int lo = 0, hi = M;
        while (lo < hi) {
            int mid = (lo + hi) >> 1;
            if (__ldg(&idx[mid]) < n) lo = mid + 1;
            else                      hi = mid;
        }
        s_bounds[t] = lo;
    }
    __syncthreads();

    // Phase 2: warp-per-row streaming segmented sum.
    const int w    = t >> 5;
    const int lane = t & 31;
    const int row  = r0 + w;
    if (row >= Nrows) return;

    const int s = s_bounds[w];
    const int e = s_bounds[w + 1];

    const int base = row * 32 + lane;             // N*32 = 8.4M, fits int
    float4 acc = self_t[base];

    // Unroll-by-2: two independent in-flight loads per iteration for MLP.
    int i = s;
    for (; i + 2 <= e; i += 2) {
        float4 v0 = __ldcs(&value[(size_t)i       * 32 + lane]);
        float4 v1 = __ldcs(&value[(size_t)(i + 1) * 32 + lane]);
        acc.x += v0.x + v1.x;
        acc.y += v0.y + v1.y;
        acc.z += v0.z + v1.z;
        acc.w += v0.w + v1.w;
    }
    if (i < e) {
        float4 v = __ldcs(&value[(size_t)i * 32 + lane]);
        acc.x += v.x;
        acc.y += v.y;
        acc.z += v.z;
        acc.w += v.w;
    }

    out[base] = acc;
}

extern "C" void kernel_launch(void* const* d_in, const int* in_sizes, int n_in,
                              void* d_out, int out_size) {
    const float* self_t = (const float*)d_in[0];   // [N, 128] f32
    const float* value  = (const float*)d_in[1];   // [M, 128] f32
    const int*   sidx   = (const int*)d_in[2];     // [M] int32 (sorted)
    // d_in[3] = pos, unused

    int Nrows = in_sizes[0] / 128;   // 262144
    int M     = in_sizes[2];         // 1048576

    int blocks = (Nrows + ROWS_PER_BLOCK - 1) / ROWS_PER_BLOCK;  // 16384
    fused_scatter_add_kernel<<<blocks, THREADS>>>(
        sidx,
        (const float4*)self_t, (const float4*)value,
        (float4*)d_out, M, Nrows);
}

// round 13
// speedup vs baseline: 1.6841x; 1.6841x over previous
#include <cuda_runtime.h>
#include <cstdint>

// Problem constants (fixed by the reference): N=262144 output rows, D=128 f32.
// M = 1048576 value rows, sorted_index is sorted -> segmented sum, no atomics.
#define MAX_N 262144
#define ROWS_PER_BLOCK 8   // 8 warps/block, warp-per-row (proven 86.8% DRAM)

// Scratch: segment start offsets, g_start[n] = lower_bound(sorted_index, n).
__device__ int g_start[MAX_N + 1];

// Kernel 1: linear-scan bounds. Thread i covers output rows (idx[i-1], idx[i]]:
// for each such n, lower_bound(idx, n) == i. Coalesced streaming reads, no
// dependent-load chains (vs 21-step binary search). Thread M handles the tail.
__global__ void compute_bounds_scan_kernel(const int* __restrict__ idx,
                                           int M, int Nrows) {
    int i = blockIdx.x * blockDim.x + threadIdx.x;
    if (i > M) return;
    int prev = (i == 0) ? -1 : idx[i - 1];
    int cur  = (i == M) ? Nrows : idx[i];
    for (int n = prev + 1; n <= cur; n++)
        g_start[n] = i;
}

// Kernel 2: warp-per-row segmented sum (identical to the 86.8%-DRAM R9 kernel).
// D=128 floats = 32 float4 = one per lane.
__global__ void __launch_bounds__(32 * ROWS_PER_BLOCK)
scatter_add_rows_kernel(const float4* __restrict__ self_t,
                        const float4* __restrict__ value,
                        float4* __restrict__ out,
                        int Nrows) {
    int row  = blockIdx.x * ROWS_PER_BLOCK + (threadIdx.x >> 5);
    int lane = threadIdx.x & 31;
    if (row >= Nrows) return;

    int s = g_start[row];
    int e = g_start[row + 1];

    int base = row * 32 + lane;           // N*32 = 8.4M, fits int
    float4 acc = self_t[base];

    for (int i = s; i < e; i++) {
        float4 v = __ldg(&value[(size_t)i * 32 + lane]);
        acc.x += v.x;
        acc.y += v.y;
        acc.z += v.z;
        acc.w += v.w;
    }
    out[base] = acc;
}

extern "C" void kernel_launch(void* const* d_in, const int* in_sizes, int n_in,
                              void* d_out, int out_size) {
    const float* self_t = (const float*)d_in[0];   // [N, 128] f32
    const float* value  = (const float*)d_in[1];   // [M, 128] f32
    const int*   sidx   = (const int*)d_in[2];     // [M] int32 (sorted)
    // d_in[3] = pos, unused

    int Nrows = in_sizes[0] / 128;   // 262144
    int M     = in_sizes[2];         // 1048576

    // Kernel 1: linear-scan fill of g_start[0..Nrows] (M+1 threads)
    {
        int threads = 256;
        int blocks = (M + 1 + threads - 1) / threads;
        compute_bounds_scan_kernel<<<blocks, threads>>>(sidx, M, Nrows);
    }

    // Kernel 2: streaming segmented add, warp per output row
    {
        int threads = 32 * ROWS_PER_BLOCK;
        int blocks = (Nrows + ROWS_PER_BLOCK - 1) / ROWS_PER_BLOCK;
        scatter_add_rows_kernel<<<blocks, threads>>>(
            (const float4*)self_t, (const float4*)value,
            (float4*)d_out, Nrows);
    }
}